// round 16
// baseline (speedup 1.0000x reference)
#include <cuda_runtime.h>
#include <math.h>

typedef unsigned long long ull;

#define DINL __device__ __forceinline__

DINL ull pk2(float lo, float hi) {
    ull r; asm("mov.b64 %0, {%1,%2};" : "=l"(r) : "f"(lo), "f"(hi)); return r;
}
DINL void upk2(ull v, float& lo, float& hi) {
    asm("mov.b64 {%0,%1}, %2;" : "=f"(lo), "=f"(hi) : "l"(v));
}
DINL ull ffma2(ull a, ull b, ull c) {
    ull d; asm("fma.rn.f32x2 %0, %1, %2, %3;" : "=l"(d) : "l"(a), "l"(b), "l"(c)); return d;
}
DINL float ex2f(float x) {
    float y; asm("ex2.approx.f32 %0, %1;" : "=f"(y) : "f"(x)); return y;
}
DINL float gelu_exact(float x) {
    return 0.5f * x * (1.0f + erff(x * 0.7071067811865476f));
}

constexpr int B  = 2;
constexpr int C  = 64;
constexpr int HW = 48;
constexpr int N  = 2304;   // 48*48
constexpr int H  = 8;      // heads
constexpr int D  = 8;      // head dim
constexpr int KQ = 576;    // keys per quarter (key-split 4)

// ---------------- scratch (device globals; no allocs allowed) ----------------
__device__ __align__(16) float g_xt[2 * B * N * C];           // [s][b][n][c]  n = w*48+h, c contiguous
__device__ __align__(16) float g_qkv[2][3][B * H * N * D];    // [stream][q,k,v] (b,h,n,d)
__device__ __align__(16) float g_pacc[4 * 4 * H * N * D];     // [z][quarter][h][n][d]  (CTA-contiguous stores)
__device__ __align__(16) float g_psum[4 * 4 * H * N];         // [z][quarter][h][n]  sum of p
__device__ __align__(16) float g_wefft[2][C * C];             // effective weights, [att][k*64+o]
__device__ __align__(16) float g_beff[C];                     // effective bias

// ---------------- kernel 0: staged transpose (+depth conv/ReLU/upsample) ----------------
__global__ void k_tr(const float* __restrict__ rgb,
                     const float* __restrict__ depth,
                     const float* __restrict__ w_exp,
                     const float* __restrict__ b_exp) {
    __shared__ float tile[64 * 49];
    int h = blockIdx.x, b = blockIdx.y, s = blockIdx.z;
    int tid = threadIdx.x;

    if (s == 0) {
        for (int idx = tid; idx < 64 * 48; idx += 256) {
            int c = idx / 48, w = idx % 48;
            tile[c * 49 + w] = rgb[(b * C + c) * N + h * HW + w];
        }
    } else {
        float sy = h * 0.5f - 0.25f;
        float fy = floorf(sy);
        float wy1 = sy - fy, wy0 = 1.0f - wy1;
        int y0 = max((int)fy, 0), y1 = min((int)fy + 1, 23);
        const float* dp = depth + b * 576;
        for (int idx = tid; idx < 64 * 48; idx += 256) {
            int c = idx / 48, w = idx % 48;
            float sx = w * 0.5f - 0.25f;
            float fx = floorf(sx);
            float wx1 = sx - fx, wx0 = 1.0f - wx1;
            int x0 = max((int)fx, 0), x1 = min((int)fx + 1, 23);
            float d00 = dp[y0 * 24 + x0], d01 = dp[y0 * 24 + x1];
            float d10 = dp[y1 * 24 + x0], d11 = dp[y1 * 24 + x1];
            float we = w_exp[c], be = b_exp[c];
            float v = wy0 * wx0 * fmaxf(fmaf(we, d00, be), 0.f)
                    + wy0 * wx1 * fmaxf(fmaf(we, d01, be), 0.f)
                    + wy1 * wx0 * fmaxf(fmaf(we, d10, be), 0.f)
                    + wy1 * wx1 * fmaxf(fmaf(we, d11, be), 0.f);
            tile[c * 49 + w] = v;
        }
    }
    __syncthreads();

    float* xb = g_xt + ((size_t)(s * B + b) * N) * C;
    for (int idx = tid; idx < 48 * 64; idx += 256) {
        int w = idx / 64, c = idx % 64;
        xb[(w * HW + h) * C + c] = tile[c * 49 + w];
    }
}

// ---------------- kernel 1: fused QKV GEMMs (fine grid: 1 matrix/block) + weff side-blocks ----------------
__global__ void k_qkv(const float* __restrict__ wq0, const float* __restrict__ wk0, const float* __restrict__ wv0,
                      const float* __restrict__ wq1, const float* __restrict__ wk1, const float* __restrict__ wv1,
                      const float* __restrict__ wrp, const float* __restrict__ brp,
                      const float* __restrict__ wdp, const float* __restrict__ bdp,
                      const float* __restrict__ wcomp, const float* __restrict__ bcomp) {
    extern __shared__ float sm[];
    int tid = threadIdx.x;           // 192 threads

    if (blockIdx.x == 48) {
        int blkid = blockIdx.y * 2 + blockIdx.z;       // 0..11
        if (blkid >= 8) return;
        __shared__ float sWc[8][128];
        __shared__ float sRed[8][64];
        for (int idx = tid; idx < 8 * 128; idx += 192) {
            int oo = idx >> 7, cc = idx & 127;
            sWc[oo][cc] = wcomp[(blkid * 8 + oo) * 128 + cc];
        }
        __syncthreads();
        for (int idx = tid; idx < 1024; idx += 192) {
            int oo = idx >> 7, rem = idx & 127;
            int att = rem >> 6, k = rem & 63;
            const float* wp = att ? wdp : wrp;
            float acc = 0.f;
#pragma unroll
            for (int c = 0; c < 64; c++)
                acc = fmaf(sWc[oo][att * 64 + c], wp[c * 64 + k], acc);
            g_wefft[att][k * 64 + blkid * 8 + oo] = acc;
        }
        for (int idx = tid; idx < 512; idx += 192) {
            int oo = idx >> 6, cc = idx & 63;
            sRed[oo][cc] = sWc[oo][cc] * brp[cc] + sWc[oo][64 + cc] * bdp[cc];
        }
        __syncthreads();
        if (tid < 8) {
            float a = bcomp[blkid * 8 + tid];
            for (int c = 0; c < 64; c++) a += sRed[tid][c];
            g_beff[blkid * 8 + tid] = a;
        }
        return;
    }

    float* sX  = sm;                 // [n_local][c] stride 68 -> 13056 B
    float* sWt = sm + 48 * 68;       // [c][ocl] stride 68 -> 17408 B

    int w = blockIdx.x;
    int b = blockIdx.y / 3, mat = blockIdx.y % 3;
    int s = blockIdx.z;

    const float4* xtb = (const float4*)(g_xt + (((size_t)(s * B + b) * N) + (size_t)w * HW) * C);
    for (int i = tid; i < 48 * 16; i += 192) {
        int nloc = i >> 4, c4 = i & 15;
        *(float4*)&sX[nloc * 68 + c4 * 4] = xtb[i];
    }

    const float* wm;
    if (s == 0) wm = (mat == 0) ? wq0 : (mat == 1 ? wk0 : wv0);
    else        wm = (mat == 0) ? wq1 : (mat == 1 ? wk1 : wv1);
    for (int idx = tid; idx < 64 * 64; idx += 192) {
        int ocl = idx >> 6, c = idx & 63;
        sWt[c * 68 + ocl] = wm[ocl * 64 + c];
    }
    __syncthreads();

    int nl = tid % 48;
    int g  = tid / 48;        // 0..3
    int oc0 = g * 16;
    int n = w * HW + nl;

    ull acc[8];
#pragma unroll
    for (int j = 0; j < 8; j++) acc[j] = 0ull;

#pragma unroll 4
    for (int c4 = 0; c4 < 16; c4++) {
        float4 xv4 = *(const float4*)&sX[nl * 68 + c4 * 4];
        float xs[4] = {xv4.x, xv4.y, xv4.z, xv4.w};
#pragma unroll
        for (int i = 0; i < 4; i++) {
            int c = c4 * 4 + i;
            ull xp = pk2(xs[i], xs[i]);
            const ulonglong2* w2 = (const ulonglong2*)(sWt + c * 68 + oc0);
#pragma unroll
            for (int j = 0; j < 4; j++) {
                ulonglong2 wv2 = w2[j];
                acc[2 * j]     = ffma2(xp, wv2.x, acc[2 * j]);
                acc[2 * j + 1] = ffma2(xp, wv2.y, acc[2 * j + 1]);
            }
        }
    }

#pragma unroll
    for (int j = 0; j < 8; j++) {
        int ocm = oc0 + 2 * j;
        int hd = ocm >> 3, d = ocm & 7;
        float lo, hi; upk2(acc[j], lo, hi);
        *(float2*)&g_qkv[s][mat][((size_t)(b * H + hd) * N + n) * D + d] = make_float2(lo, hi);
    }
}

// ---------------- kernel 2: cross-attention (R15 exact; frozen) ----------------
__global__ void __launch_bounds__(128, 6) k_attn() {
    extern __shared__ float sm[];
    ull*    sK = (ull*)sm;                    // 288 pairs * 8 ull = 18432 B
    float4* sV = (float4*)(sm + 4608);        // 576 keys * 2 float4 = 18432 B

    int chunk = blockIdx.x;
    int h = blockIdx.y & 7, quarter = blockIdx.y >> 3;
    int z = blockIdx.z;                        // att*2+b
    int att = z >> 1, b = z & 1;
    int tid = threadIdx.x;

    // hoisted Q loads: issue before the K/V fill so DRAM/L2 latency hides under it
    int n0 = chunk * 256 + tid;
    int n1 = n0 + 128;
    const float* Qb = g_qkv[att][0] + (size_t)(b * H + h) * N * D;
    float4 qa = *(const float4*)(Qb + (size_t)n0 * D);
    float4 qb = *(const float4*)(Qb + (size_t)n0 * D + 4);
    float4 qc = *(const float4*)(Qb + (size_t)n1 * D);
    float4 qd = *(const float4*)(Qb + (size_t)n1 * D + 4);

    const float* Kg = g_qkv[1 - att][1] + ((size_t)(b * H + h) * N + quarter * KQ) * D;
    const float* Vg = g_qkv[1 - att][2] + ((size_t)(b * H + h) * N + quarter * KQ) * D;

    const float4* Vg4 = (const float4*)Vg;
    for (int i = tid; i < KQ * 2; i += 128) sV[i] = Vg4[i];
    const float4* Kg4 = (const float4*)Kg;
    for (int j = tid; j < KQ / 2; j += 128) {
        float4 a0 = Kg4[4 * j], a1 = Kg4[4 * j + 1];
        float4 c0 = Kg4[4 * j + 2], c1 = Kg4[4 * j + 3];
        ull* d = sK + j * 8;
        d[0] = pk2(a0.x, c0.x); d[1] = pk2(a0.y, c0.y);
        d[2] = pk2(a0.z, c0.z); d[3] = pk2(a0.w, c0.w);
        d[4] = pk2(a1.x, c1.x); d[5] = pk2(a1.y, c1.y);
        d[6] = pk2(a1.z, c1.z); d[7] = pk2(a1.w, c1.w);
    }
    __syncthreads();

    constexpr float QS = 0.3535533905932738f * 1.4426950408889634f; // scale * log2(e)
    constexpr float SHIFTF = -14.4269504088896f;                     // cancels in normalization

    ull qp0[8], qp1[8];
    qp0[0] = pk2(qa.x * QS, qa.x * QS); qp0[1] = pk2(qa.y * QS, qa.y * QS);
    qp0[2] = pk2(qa.z * QS, qa.z * QS); qp0[3] = pk2(qa.w * QS, qa.w * QS);
    qp0[4] = pk2(qb.x * QS, qb.x * QS); qp0[5] = pk2(qb.y * QS, qb.y * QS);
    qp0[6] = pk2(qb.z * QS, qb.z * QS); qp0[7] = pk2(qb.w * QS, qb.w * QS);
    qp1[0] = pk2(qc.x * QS, qc.x * QS); qp1[1] = pk2(qc.y * QS, qc.y * QS);
    qp1[2] = pk2(qc.z * QS, qc.z * QS); qp1[3] = pk2(qc.w * QS, qc.w * QS);
    qp1[4] = pk2(qd.x * QS, qd.x * QS); qp1[5] = pk2(qd.y * QS, qd.y * QS);
    qp1[6] = pk2(qd.z * QS, qd.z * QS); qp1[7] = pk2(qd.w * QS, qd.w * QS);

    const ull SH2  = pk2(SHIFTF, SHIFTF);
    const ull ONE2 = pk2(1.0f, 1.0f);
    const ulonglong2* sK2 = (const ulonglong2*)sK;
    const ulonglong2* sV2 = (const ulonglong2*)sV;

    ull acc0[4] = {0, 0, 0, 0}, acc1[4] = {0, 0, 0, 0};
    ull ssp0 = 0ull, ssp1 = 0ull;

#pragma unroll 2
    for (int j = 0; j < KQ / 2; j++) {
        ulonglong2 kA = sK2[4 * j],     kB = sK2[4 * j + 1];
        ulonglong2 kC = sK2[4 * j + 2], kD = sK2[4 * j + 3];
        ull t0 = ffma2(qp0[0], kA.x, SH2);
        ull t1 = ffma2(qp1[0], kA.x, SH2);
        t0 = ffma2(qp0[1], kA.y, t0); t1 = ffma2(qp1[1], kA.y, t1);
        t0 = ffma2(qp0[2], kB.x, t0); t1 = ffma2(qp1[2], kB.x, t1);
        t0 = ffma2(qp0[3], kB.y, t0); t1 = ffma2(qp1[3], kB.y, t1);
        t0 = ffma2(qp0[4], kC.x, t0); t1 = ffma2(qp1[4], kC.x, t1);
        t0 = ffma2(qp0[5], kC.y, t0); t1 = ffma2(qp1[5], kC.y, t1);
        t0 = ffma2(qp0[6], kD.x, t0); t1 = ffma2(qp1[6], kD.x, t1);
        t0 = ffma2(qp0[7], kD.y, t0); t1 = ffma2(qp1[7], kD.y, t1);

        float s00, s01, s10, s11;
        upk2(t0, s00, s01); upk2(t1, s10, s11);
        float p00 = ex2f(s00), p01 = ex2f(s01);
        float p10 = ex2f(s10), p11 = ex2f(s11);
        ssp0 = ffma2(pk2(p00, p01), ONE2, ssp0);
        ssp1 = ffma2(pk2(p10, p11), ONE2, ssp1);
        ull pp00 = pk2(p00, p00), pp01 = pk2(p01, p01);
        ull pp10 = pk2(p10, p10), pp11 = pk2(p11, p11);

        ulonglong2 vA = sV2[4 * j],     vB = sV2[4 * j + 1];
        ulonglong2 vC = sV2[4 * j + 2], vD = sV2[4 * j + 3];
        acc0[0] = ffma2(pp00, vA.x, acc0[0]); acc0[1] = ffma2(pp00, vA.y, acc0[1]);
        acc0[2] = ffma2(pp00, vB.x, acc0[2]); acc0[3] = ffma2(pp00, vB.y, acc0[3]);
        acc0[0] = ffma2(pp01, vC.x, acc0[0]); acc0[1] = ffma2(pp01, vC.y, acc0[1]);
        acc0[2] = ffma2(pp01, vD.x, acc0[2]); acc0[3] = ffma2(pp01, vD.y, acc0[3]);
        acc1[0] = ffma2(pp10, vA.x, acc1[0]); acc1[1] = ffma2(pp10, vA.y, acc1[1]);
        acc1[2] = ffma2(pp10, vB.x, acc1[2]); acc1[3] = ffma2(pp10, vB.y, acc1[3]);
        acc1[0] = ffma2(pp11, vC.x, acc1[0]); acc1[1] = ffma2(pp11, vC.y, acc1[1]);
        acc1[2] = ffma2(pp11, vD.x, acc1[2]); acc1[3] = ffma2(pp11, vD.y, acc1[3]);
    }

    float se0, so0, se1, so1;
    upk2(ssp0, se0, so0);
    upk2(ssp1, se1, so1);

    // contiguous stores: pacc[z][quarter][h][n][8]
    size_t hb = (((size_t)z * 4 + quarter) * H + h) * N;
    size_t pb0 = (hb + n0) * D;
    size_t pb1 = (hb + n1) * D;
    float4 f;
    upk2(acc0[0], f.x, f.y); upk2(acc0[1], f.z, f.w); *(float4*)&g_pacc[pb0]     = f;
    upk2(acc0[2], f.x, f.y); upk2(acc0[3], f.z, f.w); *(float4*)&g_pacc[pb0 + 4] = f;
    upk2(acc1[0], f.x, f.y); upk2(acc1[1], f.z, f.w); *(float4*)&g_pacc[pb1]     = f;
    upk2(acc1[2], f.x, f.y); upk2(acc1[3], f.z, f.w); *(float4*)&g_pacc[pb1 + 4] = f;
    g_psum[hb + n0] = se0 + so0;
    g_psum[hb + n1] = se1 + so1;
}

// ---------------- kernel 3: combine partials + (proj+compress) GEMM + GELU ----------------
// 288 blocks x 16 rows, 512 threads (occupancy 2x); coalesced psum reads.
__global__ void k_out(float* __restrict__ out) {
    extern __shared__ float sm[];
    float* sA   = sm;            // [att][r][k] stride 65 -> 2080 floats
    float* sW   = sm + 2080;     // [att][k][o]          -> 8192 floats
    float* sInv = sm + 10272;    // [att][r][h]          -> 256 floats
    float* sB   = sm + 10528;    // 64 floats

    int tid = threadIdx.x;       // 512
    int row0 = blockIdx.x * 16;
    int bb = row0 / N;
    int nb = row0 - bb * N;

    // 1/(sum over 4 quarters of psum): remapped so r is fastest -> coalesced psum reads
    if (tid < 256) {
        int att = tid >> 7, hh = (tid >> 4) & 7, r = tid & 15;
        int n = nb + r;
        int z = att * 2 + bb;
        float s = 0.f;
#pragma unroll
        for (int qq = 0; qq < 4; qq++)
            s += g_psum[(((size_t)z * 4 + qq) * H + hh) * N + n];
        sInv[(att * 16 + r) * 8 + hh] = 1.0f / s;
    }
    for (int idx = tid; idx < 2 * 64 * 64; idx += 512)
        sW[idx] = ((const float*)g_wefft)[idx];
    if (tid < 64) sB[tid] = g_beff[tid];
    __syncthreads();

    // combine: idx -> att (slowest), hh, r, half (fastest); one item per thread
    {
        int idx = tid;           // 512 items exactly
        int att  = idx >> 8;
        int rem  = idx & 255;
        int hh   = rem >> 5;          // 0..7
        int r    = (rem >> 1) & 15;   // 0..15
        int half = rem & 1;           // 0..1
        int dd   = half * 4;
        int z = att * 2 + bb;
        int n = nb + r;
        float4 x = make_float4(0.f, 0.f, 0.f, 0.f);
#pragma unroll
        for (int qq = 0; qq < 4; qq++) {
            float4 y = *(const float4*)&g_pacc[((((size_t)z * 4 + qq) * H + hh) * N + n) * D + dd];
            x.x += y.x; x.y += y.y; x.z += y.z; x.w += y.w;
        }
        float inv = sInv[(att * 16 + r) * 8 + hh];
        float* dst = sA + (att * 16 + r) * 65 + hh * 8 + dd;
        dst[0] = x.x * inv; dst[1] = x.y * inv;
        dst[2] = x.z * inv; dst[3] = x.w * inv;
    }
    __syncthreads();

    // GEMM: 512 threads, 2 outputs each (16 r x 32 o-groups of 2)
    int r = tid & 15, og = tid >> 4, o0 = og * 2;
    ull acc = 0ull;
    for (int k = 0; k < 64; k++) {
        float a0 = sA[(0 * 16 + r) * 65 + k];
        float a1 = sA[(1 * 16 + r) * 65 + k];
        ull pa0 = pk2(a0, a0), pa1 = pk2(a1, a1);
        ull u0 = *(const ull*)(sW + (0 * 64 + k) * 64 + o0);
        ull u1 = *(const ull*)(sW + (64 + k) * 64 + o0);
        acc = ffma2(pa0, u0, acc);
        acc = ffma2(pa1, u1, acc);
    }

    int n = nb + r;
    float lo, hi; upk2(acc, lo, hi);
    out[((size_t)(bb * C + o0)) * N + n]     = gelu_exact(lo + sB[o0]);
    out[((size_t)(bb * C + o0 + 1)) * N + n] = gelu_exact(hi + sB[o0 + 1]);
}

// ---------------- launch ----------------
extern "C" void kernel_launch(void* const* d_in, const int* in_sizes, int n_in,
                              void* d_out, int out_size) {
    const float* rgb    = (const float*)d_in[0];
    const float* depth  = (const float*)d_in[1];
    const float* w_exp  = (const float*)d_in[2];
    const float* b_exp  = (const float*)d_in[3];
    const float* wrq    = (const float*)d_in[4];
    const float* wrk    = (const float*)d_in[5];
    const float* wrv    = (const float*)d_in[6];
    const float* wdq    = (const float*)d_in[7];
    const float* wdk    = (const float*)d_in[8];
    const float* wdv    = (const float*)d_in[9];
    const float* wrp    = (const float*)d_in[10];
    const float* brp    = (const float*)d_in[11];
    const float* wdp    = (const float*)d_in[12];
    const float* bdp    = (const float*)d_in[13];
    const float* wcomp  = (const float*)d_in[14];
    const float* bcomp  = (const float*)d_in[15];

    const int QKV_SMEM  = (48 * 68 + 64 * 68) * 4;         // 30464
    const int ATTN_SMEM = 2 * KQ * D * 4;                  // 36864
    const int OUT_SMEM  = (2080 + 8192 + 256 + 64) * 4;    // 42368

    cudaFuncSetAttribute(k_qkv,  cudaFuncAttributeMaxDynamicSharedMemorySize, QKV_SMEM);
    cudaFuncSetAttribute(k_attn, cudaFuncAttributeMaxDynamicSharedMemorySize, ATTN_SMEM);
    cudaFuncSetAttribute(k_out,  cudaFuncAttributeMaxDynamicSharedMemorySize, OUT_SMEM);

    k_tr<<<dim3(48, 2, 2), 256>>>(rgb, depth, w_exp, b_exp);
    k_qkv<<<dim3(49, 6, 2), 192, QKV_SMEM>>>(wrq, wrk, wrv, wdq, wdk, wdv,
                                             wrp, brp, wdp, bdp, wcomp, bcomp);
    k_attn<<<dim3(9, 32, 4), 128, ATTN_SMEM>>>();
    k_out<<<288, 512, OUT_SMEM>>>((float*)d_out);
}

// round 17
// speedup vs baseline: 1.0147x; 1.0147x over previous
#include <cuda_runtime.h>
#include <math.h>

typedef unsigned long long ull;

#define DINL __device__ __forceinline__

DINL ull pk2(float lo, float hi) {
    ull r; asm("mov.b64 %0, {%1,%2};" : "=l"(r) : "f"(lo), "f"(hi)); return r;
}
DINL void upk2(ull v, float& lo, float& hi) {
    asm("mov.b64 {%0,%1}, %2;" : "=f"(lo), "=f"(hi) : "l"(v));
}
DINL ull ffma2(ull a, ull b, ull c) {
    ull d; asm("fma.rn.f32x2 %0, %1, %2, %3;" : "=l"(d) : "l"(a), "l"(b), "l"(c)); return d;
}
DINL float ex2f(float x) {
    float y; asm("ex2.approx.f32 %0, %1;" : "=f"(y) : "f"(x)); return y;
}
DINL float gelu_exact(float x) {
    return 0.5f * x * (1.0f + erff(x * 0.7071067811865476f));
}

constexpr int B  = 2;
constexpr int C  = 64;
constexpr int HW = 48;
constexpr int N  = 2304;   // 48*48
constexpr int H  = 8;      // heads
constexpr int D  = 8;      // head dim
constexpr int KQ = 576;    // keys per quarter (key-split 4)

// ---------------- scratch (device globals; no allocs allowed) ----------------
__device__ __align__(16) float g_xt[2 * B * N * C];           // [s][b][n][c]  n = w*48+h, c contiguous
__device__ __align__(16) float g_qkv[2][3][B * H * N * D];    // [stream][q,k,v] (b,h,n,d)
__device__ __align__(16) float g_pacc[4 * 4 * H * N * D];     // [z][quarter][h][n][d]  (CTA-contiguous stores)
__device__ __align__(16) float g_psum[4 * 4 * H * N];         // [z][quarter][h][n]  sum of p
__device__ __align__(16) float g_wefft[2][C * C];             // effective weights, [att][k*64+o]
__device__ __align__(16) float g_beff[C];                     // effective bias

// ---------------- kernel 0: staged transpose (+depth conv/ReLU/upsample) ----------------
__global__ void k_tr(const float* __restrict__ rgb,
                     const float* __restrict__ depth,
                     const float* __restrict__ w_exp,
                     const float* __restrict__ b_exp) {
    __shared__ float tile[64 * 49];
    int h = blockIdx.x, b = blockIdx.y, s = blockIdx.z;
    int tid = threadIdx.x;

    if (s == 0) {
        for (int idx = tid; idx < 64 * 48; idx += 256) {
            int c = idx / 48, w = idx % 48;
            tile[c * 49 + w] = rgb[(b * C + c) * N + h * HW + w];
        }
    } else {
        float sy = h * 0.5f - 0.25f;
        float fy = floorf(sy);
        float wy1 = sy - fy, wy0 = 1.0f - wy1;
        int y0 = max((int)fy, 0), y1 = min((int)fy + 1, 23);
        const float* dp = depth + b * 576;
        for (int idx = tid; idx < 64 * 48; idx += 256) {
            int c = idx / 48, w = idx % 48;
            float sx = w * 0.5f - 0.25f;
            float fx = floorf(sx);
            float wx1 = sx - fx, wx0 = 1.0f - wx1;
            int x0 = max((int)fx, 0), x1 = min((int)fx + 1, 23);
            float d00 = dp[y0 * 24 + x0], d01 = dp[y0 * 24 + x1];
            float d10 = dp[y1 * 24 + x0], d11 = dp[y1 * 24 + x1];
            float we = w_exp[c], be = b_exp[c];
            float v = wy0 * wx0 * fmaxf(fmaf(we, d00, be), 0.f)
                    + wy0 * wx1 * fmaxf(fmaf(we, d01, be), 0.f)
                    + wy1 * wx0 * fmaxf(fmaf(we, d10, be), 0.f)
                    + wy1 * wx1 * fmaxf(fmaf(we, d11, be), 0.f);
            tile[c * 49 + w] = v;
        }
    }
    __syncthreads();

    float* xb = g_xt + ((size_t)(s * B + b) * N) * C;
    for (int idx = tid; idx < 48 * 64; idx += 256) {
        int w = idx / 64, c = idx % 64;
        xb[(w * HW + h) * C + c] = tile[c * 49 + w];
    }
}

// ---------------- kernel 1: fused QKV GEMMs (fine grid: 1 matrix/block) + weff side-blocks ----------------
__global__ void k_qkv(const float* __restrict__ wq0, const float* __restrict__ wk0, const float* __restrict__ wv0,
                      const float* __restrict__ wq1, const float* __restrict__ wk1, const float* __restrict__ wv1,
                      const float* __restrict__ wrp, const float* __restrict__ brp,
                      const float* __restrict__ wdp, const float* __restrict__ bdp,
                      const float* __restrict__ wcomp, const float* __restrict__ bcomp) {
    extern __shared__ float sm[];
    int tid = threadIdx.x;           // 192 threads

    if (blockIdx.x == 48) {
        int blkid = blockIdx.y * 2 + blockIdx.z;       // 0..11
        if (blkid >= 8) return;
        __shared__ float sWc[8][128];
        __shared__ float sRed[8][64];
        for (int idx = tid; idx < 8 * 128; idx += 192) {
            int oo = idx >> 7, cc = idx & 127;
            sWc[oo][cc] = wcomp[(blkid * 8 + oo) * 128 + cc];
        }
        __syncthreads();
        for (int idx = tid; idx < 1024; idx += 192) {
            int oo = idx >> 7, rem = idx & 127;
            int att = rem >> 6, k = rem & 63;
            const float* wp = att ? wdp : wrp;
            float acc = 0.f;
#pragma unroll
            for (int c = 0; c < 64; c++)
                acc = fmaf(sWc[oo][att * 64 + c], wp[c * 64 + k], acc);
            g_wefft[att][k * 64 + blkid * 8 + oo] = acc;
        }
        for (int idx = tid; idx < 512; idx += 192) {
            int oo = idx >> 6, cc = idx & 63;
            sRed[oo][cc] = sWc[oo][cc] * brp[cc] + sWc[oo][64 + cc] * bdp[cc];
        }
        __syncthreads();
        if (tid < 8) {
            float a = bcomp[blkid * 8 + tid];
            for (int c = 0; c < 64; c++) a += sRed[tid][c];
            g_beff[blkid * 8 + tid] = a;
        }
        return;
    }

    float* sX  = sm;                 // [n_local][c] stride 68 -> 13056 B
    float* sWt = sm + 48 * 68;       // [c][ocl] stride 68 -> 17408 B

    int w = blockIdx.x;
    int b = blockIdx.y / 3, mat = blockIdx.y % 3;
    int s = blockIdx.z;

    const float4* xtb = (const float4*)(g_xt + (((size_t)(s * B + b) * N) + (size_t)w * HW) * C);
    for (int i = tid; i < 48 * 16; i += 192) {
        int nloc = i >> 4, c4 = i & 15;
        *(float4*)&sX[nloc * 68 + c4 * 4] = xtb[i];
    }

    const float* wm;
    if (s == 0) wm = (mat == 0) ? wq0 : (mat == 1 ? wk0 : wv0);
    else        wm = (mat == 0) ? wq1 : (mat == 1 ? wk1 : wv1);
    for (int idx = tid; idx < 64 * 64; idx += 192) {
        int ocl = idx >> 6, c = idx & 63;
        sWt[c * 68 + ocl] = wm[ocl * 64 + c];
    }
    __syncthreads();

    int nl = tid % 48;
    int g  = tid / 48;        // 0..3
    int oc0 = g * 16;
    int n = w * HW + nl;

    ull acc[8];
#pragma unroll
    for (int j = 0; j < 8; j++) acc[j] = 0ull;

#pragma unroll 4
    for (int c4 = 0; c4 < 16; c4++) {
        float4 xv4 = *(const float4*)&sX[nl * 68 + c4 * 4];
        float xs[4] = {xv4.x, xv4.y, xv4.z, xv4.w};
#pragma unroll
        for (int i = 0; i < 4; i++) {
            int c = c4 * 4 + i;
            ull xp = pk2(xs[i], xs[i]);
            const ulonglong2* w2 = (const ulonglong2*)(sWt + c * 68 + oc0);
#pragma unroll
            for (int j = 0; j < 4; j++) {
                ulonglong2 wv2 = w2[j];
                acc[2 * j]     = ffma2(xp, wv2.x, acc[2 * j]);
                acc[2 * j + 1] = ffma2(xp, wv2.y, acc[2 * j + 1]);
            }
        }
    }

#pragma unroll
    for (int j = 0; j < 8; j++) {
        int ocm = oc0 + 2 * j;
        int hd = ocm >> 3, d = ocm & 7;
        float lo, hi; upk2(acc[j], lo, hi);
        *(float2*)&g_qkv[s][mat][((size_t)(b * H + hd) * N + n) * D + d] = make_float2(lo, hi);
    }
}

// ---------------- kernel 2: cross-attention (R15 exact; frozen) ----------------
__global__ void __launch_bounds__(128, 6) k_attn() {
    extern __shared__ float sm[];
    ull*    sK = (ull*)sm;                    // 288 pairs * 8 ull = 18432 B
    float4* sV = (float4*)(sm + 4608);        // 576 keys * 2 float4 = 18432 B

    int chunk = blockIdx.x;
    int h = blockIdx.y & 7, quarter = blockIdx.y >> 3;
    int z = blockIdx.z;                        // att*2+b
    int att = z >> 1, b = z & 1;
    int tid = threadIdx.x;

    // hoisted Q loads: issue before the K/V fill so DRAM/L2 latency hides under it
    int n0 = chunk * 256 + tid;
    int n1 = n0 + 128;
    const float* Qb = g_qkv[att][0] + (size_t)(b * H + h) * N * D;
    float4 qa = *(const float4*)(Qb + (size_t)n0 * D);
    float4 qb = *(const float4*)(Qb + (size_t)n0 * D + 4);
    float4 qc = *(const float4*)(Qb + (size_t)n1 * D);
    float4 qd = *(const float4*)(Qb + (size_t)n1 * D + 4);

    const float* Kg = g_qkv[1 - att][1] + ((size_t)(b * H + h) * N + quarter * KQ) * D;
    const float* Vg = g_qkv[1 - att][2] + ((size_t)(b * H + h) * N + quarter * KQ) * D;

    const float4* Vg4 = (const float4*)Vg;
    for (int i = tid; i < KQ * 2; i += 128) sV[i] = Vg4[i];
    const float4* Kg4 = (const float4*)Kg;
    for (int j = tid; j < KQ / 2; j += 128) {
        float4 a0 = Kg4[4 * j], a1 = Kg4[4 * j + 1];
        float4 c0 = Kg4[4 * j + 2], c1 = Kg4[4 * j + 3];
        ull* d = sK + j * 8;
        d[0] = pk2(a0.x, c0.x); d[1] = pk2(a0.y, c0.y);
        d[2] = pk2(a0.z, c0.z); d[3] = pk2(a0.w, c0.w);
        d[4] = pk2(a1.x, c1.x); d[5] = pk2(a1.y, c1.y);
        d[6] = pk2(a1.z, c1.z); d[7] = pk2(a1.w, c1.w);
    }
    __syncthreads();

    constexpr float QS = 0.3535533905932738f * 1.4426950408889634f; // scale * log2(e)
    constexpr float SHIFTF = -14.4269504088896f;                     // cancels in normalization

    ull qp0[8], qp1[8];
    qp0[0] = pk2(qa.x * QS, qa.x * QS); qp0[1] = pk2(qa.y * QS, qa.y * QS);
    qp0[2] = pk2(qa.z * QS, qa.z * QS); qp0[3] = pk2(qa.w * QS, qa.w * QS);
    qp0[4] = pk2(qb.x * QS, qb.x * QS); qp0[5] = pk2(qb.y * QS, qb.y * QS);
    qp0[6] = pk2(qb.z * QS, qb.z * QS); qp0[7] = pk2(qb.w * QS, qb.w * QS);
    qp1[0] = pk2(qc.x * QS, qc.x * QS); qp1[1] = pk2(qc.y * QS, qc.y * QS);
    qp1[2] = pk2(qc.z * QS, qc.z * QS); qp1[3] = pk2(qc.w * QS, qc.w * QS);
    qp1[4] = pk2(qd.x * QS, qd.x * QS); qp1[5] = pk2(qd.y * QS, qd.y * QS);
    qp1[6] = pk2(qd.z * QS, qd.z * QS); qp1[7] = pk2(qd.w * QS, qd.w * QS);

    const ull SH2  = pk2(SHIFTF, SHIFTF);
    const ull ONE2 = pk2(1.0f, 1.0f);
    const ulonglong2* sK2 = (const ulonglong2*)sK;
    const ulonglong2* sV2 = (const ulonglong2*)sV;

    ull acc0[4] = {0, 0, 0, 0}, acc1[4] = {0, 0, 0, 0};
    ull ssp0 = 0ull, ssp1 = 0ull;

#pragma unroll 2
    for (int j = 0; j < KQ / 2; j++) {
        ulonglong2 kA = sK2[4 * j],     kB = sK2[4 * j + 1];
        ulonglong2 kC = sK2[4 * j + 2], kD = sK2[4 * j + 3];
        ull t0 = ffma2(qp0[0], kA.x, SH2);
        ull t1 = ffma2(qp1[0], kA.x, SH2);
        t0 = ffma2(qp0[1], kA.y, t0); t1 = ffma2(qp1[1], kA.y, t1);
        t0 = ffma2(qp0[2], kB.x, t0); t1 = ffma2(qp1[2], kB.x, t1);
        t0 = ffma2(qp0[3], kB.y, t0); t1 = ffma2(qp1[3], kB.y, t1);
        t0 = ffma2(qp0[4], kC.x, t0); t1 = ffma2(qp1[4], kC.x, t1);
        t0 = ffma2(qp0[5], kC.y, t0); t1 = ffma2(qp1[5], kC.y, t1);
        t0 = ffma2(qp0[6], kD.x, t0); t1 = ffma2(qp1[6], kD.x, t1);
        t0 = ffma2(qp0[7], kD.y, t0); t1 = ffma2(qp1[7], kD.y, t1);

        float s00, s01, s10, s11;
        upk2(t0, s00, s01); upk2(t1, s10, s11);
        float p00 = ex2f(s00), p01 = ex2f(s01);
        float p10 = ex2f(s10), p11 = ex2f(s11);
        ssp0 = ffma2(pk2(p00, p01), ONE2, ssp0);
        ssp1 = ffma2(pk2(p10, p11), ONE2, ssp1);
        ull pp00 = pk2(p00, p00), pp01 = pk2(p01, p01);
        ull pp10 = pk2(p10, p10), pp11 = pk2(p11, p11);

        ulonglong2 vA = sV2[4 * j],     vB = sV2[4 * j + 1];
        ulonglong2 vC = sV2[4 * j + 2], vD = sV2[4 * j + 3];
        acc0[0] = ffma2(pp00, vA.x, acc0[0]); acc0[1] = ffma2(pp00, vA.y, acc0[1]);
        acc0[2] = ffma2(pp00, vB.x, acc0[2]); acc0[3] = ffma2(pp00, vB.y, acc0[3]);
        acc0[0] = ffma2(pp01, vC.x, acc0[0]); acc0[1] = ffma2(pp01, vC.y, acc0[1]);
        acc0[2] = ffma2(pp01, vD.x, acc0[2]); acc0[3] = ffma2(pp01, vD.y, acc0[3]);
        acc1[0] = ffma2(pp10, vA.x, acc1[0]); acc1[1] = ffma2(pp10, vA.y, acc1[1]);
        acc1[2] = ffma2(pp10, vB.x, acc1[2]); acc1[3] = ffma2(pp10, vB.y, acc1[3]);
        acc1[0] = ffma2(pp11, vC.x, acc1[0]); acc1[1] = ffma2(pp11, vC.y, acc1[1]);
        acc1[2] = ffma2(pp11, vD.x, acc1[2]); acc1[3] = ffma2(pp11, vD.y, acc1[3]);
    }

    float se0, so0, se1, so1;
    upk2(ssp0, se0, so0);
    upk2(ssp1, se1, so1);

    // contiguous stores: pacc[z][quarter][h][n][8]
    size_t hb = (((size_t)z * 4 + quarter) * H + h) * N;
    size_t pb0 = (hb + n0) * D;
    size_t pb1 = (hb + n1) * D;
    float4 f;
    upk2(acc0[0], f.x, f.y); upk2(acc0[1], f.z, f.w); *(float4*)&g_pacc[pb0]     = f;
    upk2(acc0[2], f.x, f.y); upk2(acc0[3], f.z, f.w); *(float4*)&g_pacc[pb0 + 4] = f;
    upk2(acc1[0], f.x, f.y); upk2(acc1[1], f.z, f.w); *(float4*)&g_pacc[pb1]     = f;
    upk2(acc1[2], f.x, f.y); upk2(acc1[3], f.z, f.w); *(float4*)&g_pacc[pb1 + 4] = f;
    g_psum[hb + n0] = se0 + so0;
    g_psum[hb + n1] = se1 + so1;
}

// ---------------- kernel 3: combine partials + (proj+compress) GEMM + GELU ----------------
// 288 blocks x 16 rows, 256 threads (R15 GEMM shape; sInv psum reads coalesced: r fastest)
__global__ void k_out(float* __restrict__ out) {
    extern __shared__ float sm[];
    float* sA   = sm;            // [att][r][k] stride 65 -> 2080 floats
    float* sW   = sm + 2080;     // [att][k][o]          -> 8192 floats
    float* sInv = sm + 10272;    // [att][r][h]          -> 256 floats
    float* sB   = sm + 10528;    // 64 floats

    int tid = threadIdx.x;       // 256
    int row0 = blockIdx.x * 16;
    int bb = row0 / N;
    int nb = row0 - bb * N;

    // 1/(sum over 4 quarters of psum): r fastest -> 64B coalesced psum runs
    if (tid < 256) {
        int att = tid >> 7, hh = (tid >> 4) & 7, r = tid & 15;
        int n = nb + r;
        int z = att * 2 + bb;
        float s = 0.f;
#pragma unroll
        for (int qq = 0; qq < 4; qq++)
            s += g_psum[(((size_t)z * 4 + qq) * H + hh) * N + n];
        sInv[(att * 16 + r) * 8 + hh] = 1.0f / s;
    }
    for (int idx = tid; idx < 2 * 64 * 64; idx += 256)
        sW[idx] = ((const float*)g_wefft)[idx];
    if (tid < 64) sB[tid] = g_beff[tid];
    __syncthreads();

    // combine: idx -> att (slowest), hh, r, half (fastest)
    for (int idx = tid; idx < 512; idx += 256) {
        int att  = idx >> 8;
        int rem  = idx & 255;
        int hh   = rem >> 5;          // 0..7
        int r    = (rem >> 1) & 15;   // 0..15
        int half = rem & 1;           // 0..1
        int dd   = half * 4;
        int z = att * 2 + bb;
        int n = nb + r;
        float4 x = make_float4(0.f, 0.f, 0.f, 0.f);
#pragma unroll
        for (int qq = 0; qq < 4; qq++) {
            float4 y = *(const float4*)&g_pacc[((((size_t)z * 4 + qq) * H + hh) * N + n) * D + dd];
            x.x += y.x; x.y += y.y; x.z += y.z; x.w += y.w;
        }
        float inv = sInv[(att * 16 + r) * 8 + hh];
        float* dst = sA + (att * 16 + r) * 65 + hh * 8 + dd;
        dst[0] = x.x * inv; dst[1] = x.y * inv;
        dst[2] = x.z * inv; dst[3] = x.w * inv;
    }
    __syncthreads();

    int r = tid & 15, og = tid >> 4, o0 = og * 4;
    ull acc[2] = {0, 0};
    for (int k = 0; k < 64; k++) {
        float a0 = sA[(0 * 16 + r) * 65 + k];
        float a1 = sA[(1 * 16 + r) * 65 + k];
        ull pa0 = pk2(a0, a0), pa1 = pk2(a1, a1);
        const ulonglong2* w0 = (const ulonglong2*)(sW + (0 * 64 + k) * 64 + o0);
        const ulonglong2* w1 = (const ulonglong2*)(sW + (64 + k) * 64 + o0);
        ulonglong2 u0 = w0[0], u1 = w1[0];
        acc[0] = ffma2(pa0, u0.x, acc[0]); acc[1] = ffma2(pa0, u0.y, acc[1]);
        acc[0] = ffma2(pa1, u1.x, acc[0]); acc[1] = ffma2(pa1, u1.y, acc[1]);
    }

    int n = nb + r;
#pragma unroll
    for (int j = 0; j < 2; j++) {
        float lo, hi; upk2(acc[j], lo, hi);
        int o = o0 + 2 * j;
        out[((size_t)(bb * C + o)) * N + n]     = gelu_exact(lo + sB[o]);
        out[((size_t)(bb * C + o + 1)) * N + n] = gelu_exact(hi + sB[o + 1]);
    }
}

// ---------------- launch ----------------
extern "C" void kernel_launch(void* const* d_in, const int* in_sizes, int n_in,
                              void* d_out, int out_size) {
    const float* rgb    = (const float*)d_in[0];
    const float* depth  = (const float*)d_in[1];
    const float* w_exp  = (const float*)d_in[2];
    const float* b_exp  = (const float*)d_in[3];
    const float* wrq    = (const float*)d_in[4];
    const float* wrk    = (const float*)d_in[5];
    const float* wrv    = (const float*)d_in[6];
    const float* wdq    = (const float*)d_in[7];
    const float* wdk    = (const float*)d_in[8];
    const float* wdv    = (const float*)d_in[9];
    const float* wrp    = (const float*)d_in[10];
    const float* brp    = (const float*)d_in[11];
    const float* wdp    = (const float*)d_in[12];
    const float* bdp    = (const float*)d_in[13];
    const float* wcomp  = (const float*)d_in[14];
    const float* bcomp  = (const float*)d_in[15];

    const int QKV_SMEM  = (48 * 68 + 64 * 68) * 4;         // 30464
    const int ATTN_SMEM = 2 * KQ * D * 4;                  // 36864
    const int OUT_SMEM  = (2080 + 8192 + 256 + 64) * 4;    // 42368

    cudaFuncSetAttribute(k_qkv,  cudaFuncAttributeMaxDynamicSharedMemorySize, QKV_SMEM);
    cudaFuncSetAttribute(k_attn, cudaFuncAttributeMaxDynamicSharedMemorySize, ATTN_SMEM);
    cudaFuncSetAttribute(k_out,  cudaFuncAttributeMaxDynamicSharedMemorySize, OUT_SMEM);

    k_tr<<<dim3(48, 2, 2), 256>>>(rgb, depth, w_exp, b_exp);
    k_qkv<<<dim3(49, 6, 2), 192, QKV_SMEM>>>(wrq, wrk, wrv, wdq, wdk, wdv,
                                             wrp, brp, wdp, bdp, wcomp, bcomp);
    k_attn<<<dim3(9, 32, 4), 128, ATTN_SMEM>>>();
    k_out<<<288, 256, OUT_SMEM>>>((float*)d_out);
}